// round 1
// baseline (speedup 1.0000x reference)
#include <cuda_runtime.h>
#include <math.h>

// Problem constants
#define B_  2
#define T_  2048
#define D_  1024
#define H_  16
#define DK_ 64
constexpr int   M_ROWS    = B_ * T_;            // 4096
constexpr long long OUT_ELEMS = (long long)B_ * T_ * D_;  // 4194304
constexpr float SCALE     = 0.125f;             // 1/sqrt(64)

// Scratch (device globals: no allocation allowed)
__device__ float g_Q[B_*H_*T_*DK_];
__device__ float g_K[B_*H_*T_*DK_];
__device__ float g_V[B_*H_*T_*DK_];
__device__ float g_ctx[B_*T_*D_];
__device__ float g_m[B_*H_*T_];
__device__ float g_l[B_*H_*T_];

// ---------------------------------------------------------------------------
// Tiled SGEMM body: C[m,n] = sum_k A[m,k]*W[k,n] + bias[n]
// BM=BN=128, BK=16, 256 threads, 8x8 per thread.
// HEADSPLIT: write out in [B,H,T,DK] layout instead of [M,N].
// ---------------------------------------------------------------------------
template<bool HEADSPLIT>
__device__ __forceinline__ void gemm_body(const float* __restrict__ A,
                                          const float* __restrict__ W,
                                          const float* __restrict__ bias,
                                          float* __restrict__ out)
{
    __shared__ float As[16][128];  // A tile transposed: As[k][m]
    __shared__ float Bs[16][128];  // B tile natural:    Bs[k][n]

    const int tid = threadIdx.x;
    const int tr  = tid >> 4;      // 0..15
    const int tc  = tid & 15;      // 0..15
    const int rowBase = blockIdx.y * 128;
    const int colBase = blockIdx.x * 128;

    float acc[8][8];
#pragma unroll
    for (int i = 0; i < 8; i++)
#pragma unroll
        for (int j = 0; j < 8; j++) acc[i][j] = 0.f;

    for (int k0 = 0; k0 < D_; k0 += 16) {
        // Load A tile (128x16) transposed into As
#pragma unroll
        for (int l = 0; l < 2; l++) {
            int f4   = tid + l * 256;        // 0..511 float4 slots
            int aRow = f4 >> 2;              // 0..127
            int aCol = (f4 & 3) * 4;         // 0..12
            float4 v = *(const float4*)&A[(size_t)(rowBase + aRow) * D_ + k0 + aCol];
            As[aCol + 0][aRow] = v.x;
            As[aCol + 1][aRow] = v.y;
            As[aCol + 2][aRow] = v.z;
            As[aCol + 3][aRow] = v.w;
        }
        // Load B tile (16x128)
#pragma unroll
        for (int l = 0; l < 2; l++) {
            int f4   = tid + l * 256;
            int bRow = f4 >> 5;              // 0..15
            int bCol = (f4 & 31) * 4;        // 0..124
            *(float4*)&Bs[bRow][bCol] =
                *(const float4*)&W[(size_t)(k0 + bRow) * D_ + colBase + bCol];
        }
        __syncthreads();

#pragma unroll
        for (int k = 0; k < 16; k++) {
            float a[8], b[8];
            *(float4*)&a[0] = *(float4*)&As[k][tr * 8];
            *(float4*)&a[4] = *(float4*)&As[k][tr * 8 + 4];
            *(float4*)&b[0] = *(float4*)&Bs[k][tc * 8];
            *(float4*)&b[4] = *(float4*)&Bs[k][tc * 8 + 4];
#pragma unroll
            for (int i = 0; i < 8; i++)
#pragma unroll
                for (int j = 0; j < 8; j++)
                    acc[i][j] = fmaf(a[i], b[j], acc[i][j]);
        }
        __syncthreads();
    }

    // Epilogue
#pragma unroll
    for (int i = 0; i < 8; i++) {
        int m = rowBase + tr * 8 + i;
#pragma unroll
        for (int jv = 0; jv < 2; jv++) {
            int n = colBase + tc * 8 + jv * 4;
            float4 bv = *(const float4*)&bias[n];
            float4 r;
            r.x = acc[i][jv*4+0] + bv.x;
            r.y = acc[i][jv*4+1] + bv.y;
            r.z = acc[i][jv*4+2] + bv.z;
            r.w = acc[i][jv*4+3] + bv.w;
            if (HEADSPLIT) {
                int b  = m >> 11;            // m / T_
                int t  = m & (T_ - 1);
                int h  = n >> 6;             // n / DK_
                int dk = n & 63;
                *(float4*)&out[(((size_t)(b * H_ + h) * T_) + t) * DK_ + dk] = r;
            } else {
                *(float4*)&out[(size_t)m * D_ + n] = r;
            }
        }
    }
}

__global__ __launch_bounds__(256, 2) void qkv_kernel(
    const float* __restrict__ q_inp, const float* __restrict__ k_inp,
    const float* __restrict__ v_inp,
    const float* __restrict__ Wq, const float* __restrict__ bq,
    const float* __restrict__ Wk, const float* __restrict__ bk,
    const float* __restrict__ Wv, const float* __restrict__ bv)
{
    if (blockIdx.z == 0)      gemm_body<true>(q_inp, Wq, bq, g_Q);
    else if (blockIdx.z == 1) gemm_body<true>(k_inp, Wk, bk, g_K);
    else                      gemm_body<true>(v_inp, Wv, bv, g_V);
}

__global__ __launch_bounds__(256, 2) void outproj_kernel(
    const float* __restrict__ Wo, const float* __restrict__ bo,
    float* __restrict__ out)
{
    gemm_body<false>(g_ctx, Wo, bo, out);
}

// ---------------------------------------------------------------------------
// Flash attention pass: per (q-tile 64, b*h) block. Online softmax over causal
// KV tiles; writes ctx [B,T,D] and per-row m,l for the attn writeout pass.
// 256 threads = 16x16 grid, 4x4 per thread.
// ---------------------------------------------------------------------------
__global__ __launch_bounds__(256) void flash_kernel()
{
    __shared__ float Qs[64 * 64];   // Qs[dk*64 + q]   (transposed, pre-scaled)
    __shared__ float KP[64 * 64];   // Ks[dk*64 + key] then Ps[q*64 + key]
    __shared__ float Vs[64 * 64];   // Vs[key*64 + dk]

    const int tid = threadIdx.x;
    const int ty  = tid >> 4;       // 0..15
    const int tx  = tid & 15;       // 0..15
    const int qt  = blockIdx.x;
    const int bh  = blockIdx.y;
    const int q0  = qt * 64;

    const float* Qg = g_Q + (size_t)bh * T_ * DK_;
    const float* Kg = g_K + (size_t)bh * T_ * DK_;
    const float* Vg = g_V + (size_t)bh * T_ * DK_;

    // Load Q tile transposed, scale folded in
#pragma unroll
    for (int l = 0; l < 4; l++) {
        int f4 = tid + l * 256;          // 0..1023
        int r  = f4 >> 4;                // row in tile
        int c  = (f4 & 15) * 4;          // dk
        float4 v = *(const float4*)&Qg[(size_t)(q0 + r) * DK_ + c];
        Qs[(c + 0) * 64 + r] = v.x * SCALE;
        Qs[(c + 1) * 64 + r] = v.y * SCALE;
        Qs[(c + 2) * 64 + r] = v.z * SCALE;
        Qs[(c + 3) * 64 + r] = v.w * SCALE;
    }

    float m_i[4], l_i[4], o[4][4];
#pragma unroll
    for (int i = 0; i < 4; i++) {
        m_i[i] = -INFINITY; l_i[i] = 0.f;
#pragma unroll
        for (int j = 0; j < 4; j++) o[i][j] = 0.f;
    }

    for (int kt = 0; kt <= qt; kt++) {
        const int k0 = kt * 64;
        __syncthreads();   // protect KP/Vs from previous iter (and Qs 1st iter)

        // Load K transposed + V natural
#pragma unroll
        for (int l = 0; l < 4; l++) {
            int f4 = tid + l * 256;
            int r  = f4 >> 4;
            int c  = (f4 & 15) * 4;
            float4 kv = *(const float4*)&Kg[(size_t)(k0 + r) * DK_ + c];
            KP[(c + 0) * 64 + r] = kv.x;
            KP[(c + 1) * 64 + r] = kv.y;
            KP[(c + 2) * 64 + r] = kv.z;
            KP[(c + 3) * 64 + r] = kv.w;
            *(float4*)&Vs[r * 64 + c] = *(const float4*)&Vg[(size_t)(k0 + r) * DK_ + c];
        }
        __syncthreads();

        // S = (Q*scale) K^T   (4x4 per thread)
        float s[4][4];
#pragma unroll
        for (int i = 0; i < 4; i++)
#pragma unroll
            for (int j = 0; j < 4; j++) s[i][j] = 0.f;
#pragma unroll 8
        for (int dk = 0; dk < 64; dk++) {
            float4 a = *(float4*)&Qs[dk * 64 + ty * 4];
            float4 b = *(float4*)&KP[dk * 64 + tx * 4];
            float av[4] = {a.x, a.y, a.z, a.w};
            float bv[4] = {b.x, b.y, b.z, b.w};
#pragma unroll
            for (int i = 0; i < 4; i++)
#pragma unroll
                for (int j = 0; j < 4; j++)
                    s[i][j] = fmaf(av[i], bv[j], s[i][j]);
        }

        // Causal mask (diagonal tile only)
        if (kt == qt) {
#pragma unroll
            for (int i = 0; i < 4; i++)
#pragma unroll
                for (int j = 0; j < 4; j++)
                    if (k0 + tx * 4 + j > q0 + ty * 4 + i) s[i][j] = -1e30f;
        }

        // Online softmax update (row groups of 16 lanes)
#pragma unroll
        for (int i = 0; i < 4; i++) {
            float tm = fmaxf(fmaxf(s[i][0], s[i][1]), fmaxf(s[i][2], s[i][3]));
#pragma unroll
            for (int off = 8; off > 0; off >>= 1)
                tm = fmaxf(tm, __shfl_xor_sync(0xffffffffu, tm, off));
            float mn   = fmaxf(m_i[i], tm);
            float corr = __expf(m_i[i] - mn);
            float rs = 0.f;
#pragma unroll
            for (int j = 0; j < 4; j++) {
                float p = __expf(s[i][j] - mn);
                s[i][j] = p;
                rs += p;
            }
#pragma unroll
            for (int off = 8; off > 0; off >>= 1)
                rs += __shfl_xor_sync(0xffffffffu, rs, off);
            l_i[i] = l_i[i] * corr + rs;
            m_i[i] = mn;
#pragma unroll
            for (int j = 0; j < 4; j++) o[i][j] *= corr;
        }

        __syncthreads();    // everyone done reading KP (as K)
        // Store P as Ps[q*64 + key] (float4 rows)
#pragma unroll
        for (int i = 0; i < 4; i++) {
            float4 pv = make_float4(s[i][0], s[i][1], s[i][2], s[i][3]);
            *(float4*)&KP[(ty * 4 + i) * 64 + tx * 4] = pv;
        }
        __syncthreads();

        // O += P @ V
#pragma unroll 8
        for (int key = 0; key < 64; key++) {
            float a[4];
#pragma unroll
            for (int i = 0; i < 4; i++) a[i] = KP[(ty * 4 + i) * 64 + key];
            float4 b = *(float4*)&Vs[key * 64 + tx * 4];
            float bv[4] = {b.x, b.y, b.z, b.w};
#pragma unroll
            for (int i = 0; i < 4; i++)
#pragma unroll
                for (int j = 0; j < 4; j++)
                    o[i][j] = fmaf(a[i], bv[j], o[i][j]);
        }
    }

    // Epilogue: ctx in [B,T,D] layout, plus m/l for the writeout pass
    const int b_ = bh >> 4;
    const int h  = bh & 15;
#pragma unroll
    for (int i = 0; i < 4; i++) {
        int   q   = q0 + ty * 4 + i;
        float inv = 1.f / l_i[i];
        float4 r  = make_float4(o[i][0]*inv, o[i][1]*inv, o[i][2]*inv, o[i][3]*inv);
        *(float4*)&g_ctx[((size_t)(b_ * T_ + q)) * D_ + h * DK_ + tx * 4] = r;
        if (tx == 0) {
            g_m[(size_t)bh * T_ + q] = m_i[i];
            g_l[(size_t)bh * T_ + q] = l_i[i];
        }
    }
}

// ---------------------------------------------------------------------------
// Attn writeout: per (q-tile, b*h) block, loop over all 32 KV tiles.
// Causal tiles recompute S and write exp(s-m)/l; masked tiles write zeros.
// ---------------------------------------------------------------------------
__global__ __launch_bounds__(256) void attn_out_kernel(float* __restrict__ attn_base)
{
    __shared__ float Qs[64 * 64];   // Qs[dk*64 + q], pre-scaled
    __shared__ float Ks[64 * 64];   // Ks[dk*64 + key]

    const int tid = threadIdx.x;
    const int ty  = tid >> 4;
    const int tx  = tid & 15;
    const int qt  = blockIdx.x;
    const int bh  = blockIdx.y;
    const int q0  = qt * 64;

    const float* Qg   = g_Q + (size_t)bh * T_ * DK_;
    const float* Kg   = g_K + (size_t)bh * T_ * DK_;
    float*       attn = attn_base + (size_t)bh * T_ * T_;

#pragma unroll
    for (int l = 0; l < 4; l++) {
        int f4 = tid + l * 256;
        int r  = f4 >> 4;
        int c  = (f4 & 15) * 4;
        float4 v = *(const float4*)&Qg[(size_t)(q0 + r) * DK_ + c];
        Qs[(c + 0) * 64 + r] = v.x * SCALE;
        Qs[(c + 1) * 64 + r] = v.y * SCALE;
        Qs[(c + 2) * 64 + r] = v.z * SCALE;
        Qs[(c + 3) * 64 + r] = v.w * SCALE;
    }

    float mrow[4], linv[4];
#pragma unroll
    for (int i = 0; i < 4; i++) {
        int q = q0 + ty * 4 + i;
        mrow[i] = g_m[(size_t)bh * T_ + q];
        linv[i] = 1.f / g_l[(size_t)bh * T_ + q];
    }
    __syncthreads();

    for (int kt = 0; kt < 32; kt++) {
        const int k0 = kt * 64;
        if (kt > qt) {
            // Fully masked tile: zeros
            float4 z = make_float4(0.f, 0.f, 0.f, 0.f);
#pragma unroll
            for (int i = 0; i < 4; i++) {
                int q = q0 + ty * 4 + i;
                *(float4*)&attn[(size_t)q * T_ + k0 + tx * 4] = z;
            }
            continue;
        }

        __syncthreads();   // everyone done reading Ks from previous iter
#pragma unroll
        for (int l = 0; l < 4; l++) {
            int f4 = tid + l * 256;
            int r  = f4 >> 4;
            int c  = (f4 & 15) * 4;
            float4 kv = *(const float4*)&Kg[(size_t)(k0 + r) * DK_ + c];
            Ks[(c + 0) * 64 + r] = kv.x;
            Ks[(c + 1) * 64 + r] = kv.y;
            Ks[(c + 2) * 64 + r] = kv.z;
            Ks[(c + 3) * 64 + r] = kv.w;
        }
        __syncthreads();

        float s[4][4];
#pragma unroll
        for (int i = 0; i < 4; i++)
#pragma unroll
            for (int j = 0; j < 4; j++) s[i][j] = 0.f;
#pragma unroll 8
        for (int dk = 0; dk < 64; dk++) {
            float4 a = *(float4*)&Qs[dk * 64 + ty * 4];
            float4 b = *(float4*)&Ks[dk * 64 + tx * 4];
            float av[4] = {a.x, a.y, a.z, a.w};
            float bv[4] = {b.x, b.y, b.z, b.w};
#pragma unroll
            for (int i = 0; i < 4; i++)
#pragma unroll
                for (int j = 0; j < 4; j++)
                    s[i][j] = fmaf(av[i], bv[j], s[i][j]);
        }

#pragma unroll
        for (int i = 0; i < 4; i++) {
            int q = q0 + ty * 4 + i;
            float4 r;
            float p[4];
#pragma unroll
            for (int j = 0; j < 4; j++) {
                int key = k0 + tx * 4 + j;
                p[j] = (key <= q) ? __expf(s[i][j] - mrow[i]) * linv[i] : 0.f;
            }
            r.x = p[0]; r.y = p[1]; r.z = p[2]; r.w = p[3];
            *(float4*)&attn[(size_t)q * T_ + k0 + tx * 4] = r;
        }
    }
}

// ---------------------------------------------------------------------------
extern "C" void kernel_launch(void* const* d_in, const int* in_sizes, int n_in,
                              void* d_out, int out_size)
{
    (void)in_sizes; (void)n_in; (void)out_size;
    const float* q_inp = (const float*)d_in[0];
    const float* k_inp = (const float*)d_in[1];
    const float* v_inp = (const float*)d_in[2];
    // d_in[3] = attn_mask (static causal; not needed)
    const float* Wq = (const float*)d_in[4];
    const float* bq = (const float*)d_in[5];
    const float* Wk = (const float*)d_in[6];
    const float* bk = (const float*)d_in[7];
    const float* Wv = (const float*)d_in[8];
    const float* bv = (const float*)d_in[9];
    const float* Wo = (const float*)d_in[10];
    const float* bo = (const float*)d_in[11];
    float* out = (float*)d_out;

    // 1) Q/K/V projections -> head-split scratch
    qkv_kernel<<<dim3(8, 32, 3), 256>>>(q_inp, k_inp, v_inp,
                                        Wq, bq, Wk, bk, Wv, bv);
    // 2) Flash attention -> ctx + (m,l)
    flash_kernel<<<dim3(32, 32), 256>>>();
    // 3) attn writeout (recompute scores)
    attn_out_kernel<<<dim3(32, 32), 256>>>(out + OUT_ELEMS);
    // 4) output projection
    outproj_kernel<<<dim3(8, 32), 256>>>(Wo, bo, out);
}

// round 3
// speedup vs baseline: 2.8648x; 2.8648x over previous
#include <cuda_runtime.h>
#include <math.h>
#include <stdint.h>

#define B_  2
#define T_  2048
#define D_  1024
#define H_  16
#define DK_ 64
constexpr long long OUT_ELEMS = (long long)B_ * T_ * D_;  // 4194304
constexpr float SCALE = 0.125f;

// Scratch (device globals)
__device__ float g_Q[B_*H_*T_*DK_];
__device__ float g_K[B_*H_*T_*DK_];
__device__ float g_V[B_*H_*T_*DK_];
__device__ float g_ctx[B_*T_*D_];
__device__ float g_m[B_*H_*T_];
__device__ float g_l[B_*H_*T_];

// ---------------------------------------------------------------------------
// tf32 helpers
// ---------------------------------------------------------------------------
__device__ __forceinline__ uint32_t f2tf(float f) {
    uint32_t u;
    asm("cvt.rna.tf32.f32 %0, %1;" : "=r"(u) : "f"(f));
    return u;
}

__device__ __forceinline__ void mma_tf32(float c[4],
                                         uint32_t a0, uint32_t a1, uint32_t a2, uint32_t a3,
                                         uint32_t b0, uint32_t b1) {
    asm volatile(
        "mma.sync.aligned.m16n8k8.row.col.f32.tf32.tf32.f32 "
        "{%0,%1,%2,%3}, {%4,%5,%6,%7}, {%8,%9}, {%0,%1,%2,%3};"
        : "+f"(c[0]), "+f"(c[1]), "+f"(c[2]), "+f"(c[3])
        : "r"(a0), "r"(a1), "r"(a2), "r"(a3), "r"(b0), "r"(b1));
}

// ---------------------------------------------------------------------------
// Projection GEMM: C[m,n] = A[m,:] @ W[:,n] + bias[n]
// BM=BN=128, BK=32, 256 threads = 8 warps (2x4), warp tile 64x32.
// As[m][k] stride 36 (4g+t conflict-free), Bs[k][n] stride 132.
// ---------------------------------------------------------------------------
template<bool HEADSPLIT>
__device__ __forceinline__ void gemm_mma(const float* __restrict__ A,
                                         const float* __restrict__ W,
                                         const float* __restrict__ bias,
                                         float* __restrict__ out)
{
    __shared__ uint32_t As[128 * 36];
    __shared__ uint32_t Bs[32 * 132];

    const int tid  = threadIdx.x;
    const int wid  = tid >> 5;
    const int lane = tid & 31;
    const int g    = lane >> 2;      // 0..7
    const int t    = lane & 3;       // 0..3
    const int wm   = wid >> 2;       // 0..1 -> 64 rows
    const int wn   = wid & 3;        // 0..3 -> 32 cols
    const int rowBase = blockIdx.y * 128;
    const int colBase = blockIdx.x * 128;

    float acc[4][4][4];
#pragma unroll
    for (int i = 0; i < 4; i++)
#pragma unroll
        for (int j = 0; j < 4; j++)
#pragma unroll
            for (int r = 0; r < 4; r++) acc[i][j][r] = 0.f;

    for (int k0 = 0; k0 < D_; k0 += 32) {
        __syncthreads();
        // A tile 128x32 (1024 float4, 4 per thread)
#pragma unroll
        for (int l = 0; l < 4; l++) {
            int idx = tid + l * 256;
            int r   = idx >> 3;
            int c4  = (idx & 7) * 4;
            float4 v = *(const float4*)&A[(size_t)(rowBase + r) * D_ + k0 + c4];
            uint4 u = make_uint4(f2tf(v.x), f2tf(v.y), f2tf(v.z), f2tf(v.w));
            *(uint4*)&As[r * 36 + c4] = u;
        }
        // B tile 32x128
#pragma unroll
        for (int l = 0; l < 4; l++) {
            int idx = tid + l * 256;
            int r   = idx >> 5;
            int c4  = (idx & 31) * 4;
            float4 v = *(const float4*)&W[(size_t)(k0 + r) * D_ + colBase + c4];
            uint4 u = make_uint4(f2tf(v.x), f2tf(v.y), f2tf(v.z), f2tf(v.w));
            *(uint4*)&Bs[r * 132 + c4] = u;
        }
        __syncthreads();

#pragma unroll
        for (int kk = 0; kk < 4; kk++) {
            const int kb = kk * 8;
            uint32_t a[4][4];
#pragma unroll
            for (int mt = 0; mt < 4; mt++) {
                int m = wm * 64 + mt * 16;
                a[mt][0] = As[(m + g)     * 36 + kb + t];
                a[mt][1] = As[(m + g + 8) * 36 + kb + t];
                a[mt][2] = As[(m + g)     * 36 + kb + t + 4];
                a[mt][3] = As[(m + g + 8) * 36 + kb + t + 4];
            }
#pragma unroll
            for (int nt = 0; nt < 4; nt++) {
                int n = wn * 32 + nt * 8;
                uint32_t b0 = Bs[(kb + t)     * 132 + n + g];
                uint32_t b1 = Bs[(kb + t + 4) * 132 + n + g];
#pragma unroll
                for (int mt = 0; mt < 4; mt++)
                    mma_tf32(acc[mt][nt], a[mt][0], a[mt][1], a[mt][2], a[mt][3], b0, b1);
            }
        }
    }

    // Epilogue: c0/c1 -> (row g, col 2t/2t+1); c2/c3 -> row g+8
#pragma unroll
    for (int mt = 0; mt < 4; mt++) {
#pragma unroll
        for (int nt = 0; nt < 4; nt++) {
            int n = colBase + wn * 32 + nt * 8 + 2 * t;
            float2 bv = *(const float2*)&bias[n];
#pragma unroll
            for (int rr = 0; rr < 2; rr++) {
                int m = rowBase + wm * 64 + mt * 16 + g + rr * 8;
                float2 rv;
                rv.x = acc[mt][nt][rr * 2 + 0] + bv.x;
                rv.y = acc[mt][nt][rr * 2 + 1] + bv.y;
                if (HEADSPLIT) {
                    int b  = m >> 11;
                    int tt = m & (T_ - 1);
                    int h  = n >> 6;
                    int dk = n & 63;
                    *(float2*)&out[(((size_t)(b * H_ + h) * T_) + tt) * DK_ + dk] = rv;
                } else {
                    *(float2*)&out[(size_t)m * D_ + n] = rv;
                }
            }
        }
    }
}

__global__ __launch_bounds__(256) void qkv_kernel(
    const float* __restrict__ q_inp, const float* __restrict__ k_inp,
    const float* __restrict__ v_inp,
    const float* __restrict__ Wq, const float* __restrict__ bq,
    const float* __restrict__ Wk, const float* __restrict__ bk,
    const float* __restrict__ Wv, const float* __restrict__ bv)
{
    if (blockIdx.z == 0)      gemm_mma<true>(q_inp, Wq, bq, g_Q);
    else if (blockIdx.z == 1) gemm_mma<true>(k_inp, Wk, bk, g_K);
    else                      gemm_mma<true>(v_inp, Wv, bv, g_V);
}

__global__ __launch_bounds__(256) void outproj_kernel(
    const float* __restrict__ Wo, const float* __restrict__ bo,
    float* __restrict__ out)
{
    gemm_mma<false>(g_ctx, Wo, bo, out);
}

// ---------------------------------------------------------------------------
// Flash attention with tf32 mma. 128 threads = 4 warps, q-tile 64.
// Warp w owns q rows [w*16, w*16+16). Dynamic smem: Qs | KP | Vs (stride 68).
// ---------------------------------------------------------------------------
extern __shared__ uint32_t fsm[];

__global__ __launch_bounds__(128) void flash_kernel()
{
    uint32_t* Qs = fsm;                 // [64][68]  Q*scale (tf32), [m][k]
    uint32_t* KP = fsm + 64 * 68;       // K as [key][dk], later P as [q][key]
    uint32_t* Vs = fsm + 2 * 64 * 68;   // V as [key][dk]

    const int tid  = threadIdx.x;
    const int wid  = tid >> 5;
    const int lane = tid & 31;
    const int g    = lane >> 2;
    const int t    = lane & 3;
    const int qt   = blockIdx.x;
    const int bh   = blockIdx.y;
    const int q0   = qt * 64;
    const int m0   = wid * 16;

    const float* Qg = g_Q + (size_t)bh * T_ * DK_;
    const float* Kg = g_K + (size_t)bh * T_ * DK_;
    const float* Vg = g_V + (size_t)bh * T_ * DK_;

    // Load Q tile (scaled, tf32)
#pragma unroll
    for (int l = 0; l < 8; l++) {
        int idx = tid + l * 128;
        int r   = idx >> 4;
        int c4  = (idx & 15) * 4;
        float4 v = *(const float4*)&Qg[(size_t)(q0 + r) * DK_ + c4];
        uint4 u = make_uint4(f2tf(v.x * SCALE), f2tf(v.y * SCALE),
                             f2tf(v.z * SCALE), f2tf(v.w * SCALE));
        *(uint4*)&Qs[r * 68 + c4] = u;
    }

    float m_i[2] = {-INFINITY, -INFINITY};
    float l_i[2] = {0.f, 0.f};
    float o[8][4];
#pragma unroll
    for (int nt = 0; nt < 8; nt++)
#pragma unroll
        for (int r = 0; r < 4; r++) o[nt][r] = 0.f;

    for (int kt = 0; kt <= qt; kt++) {
        const int k0 = kt * 64;
        __syncthreads();   // prev iter's PV reads done (and Qs 1st iter)
#pragma unroll
        for (int l = 0; l < 8; l++) {
            int idx = tid + l * 128;
            int r   = idx >> 4;
            int c4  = (idx & 15) * 4;
            float4 kv = *(const float4*)&Kg[(size_t)(k0 + r) * DK_ + c4];
            *(uint4*)&KP[r * 68 + c4] =
                make_uint4(f2tf(kv.x), f2tf(kv.y), f2tf(kv.z), f2tf(kv.w));
            float4 vv = *(const float4*)&Vg[(size_t)(k0 + r) * DK_ + c4];
            *(uint4*)&Vs[r * 68 + c4] =
                make_uint4(f2tf(vv.x), f2tf(vv.y), f2tf(vv.z), f2tf(vv.w));
        }
        __syncthreads();

        // S = Q K^T
        float sc[8][4];
#pragma unroll
        for (int nt = 0; nt < 8; nt++)
#pragma unroll
            for (int r = 0; r < 4; r++) sc[nt][r] = 0.f;
#pragma unroll
        for (int kk = 0; kk < 8; kk++) {
            const int kb = kk * 8;
            uint32_t a0 = Qs[(m0 + g)     * 68 + kb + t];
            uint32_t a1 = Qs[(m0 + g + 8) * 68 + kb + t];
            uint32_t a2 = Qs[(m0 + g)     * 68 + kb + t + 4];
            uint32_t a3 = Qs[(m0 + g + 8) * 68 + kb + t + 4];
#pragma unroll
            for (int nt = 0; nt < 8; nt++) {
                uint32_t b0 = KP[(nt * 8 + g) * 68 + kb + t];
                uint32_t b1 = KP[(nt * 8 + g) * 68 + kb + t + 4];
                mma_tf32(sc[nt], a0, a1, a2, a3, b0, b1);
            }
        }

        // Causal mask on diagonal tile
        if (kt == qt) {
#pragma unroll
            for (int nt = 0; nt < 8; nt++)
#pragma unroll
                for (int r = 0; r < 4; r++) {
                    int row = q0 + m0 + g + (r >> 1) * 8;
                    int col = k0 + nt * 8 + 2 * t + (r & 1);
                    if (col > row) sc[nt][r] = -1e30f;
                }
        }

        // Online softmax (2 rows per thread; quad = lanes sharing g)
#pragma unroll
        for (int rr = 0; rr < 2; rr++) {
            float tm = -INFINITY;
#pragma unroll
            for (int nt = 0; nt < 8; nt++)
                tm = fmaxf(tm, fmaxf(sc[nt][rr * 2], sc[nt][rr * 2 + 1]));
            tm = fmaxf(tm, __shfl_xor_sync(0xffffffffu, tm, 1));
            tm = fmaxf(tm, __shfl_xor_sync(0xffffffffu, tm, 2));
            float mn   = fmaxf(m_i[rr], tm);
            float corr = __expf(m_i[rr] - mn);
            float rs = 0.f;
#pragma unroll
            for (int nt = 0; nt < 8; nt++) {
                float p0 = __expf(sc[nt][rr * 2]     - mn);
                float p1 = __expf(sc[nt][rr * 2 + 1] - mn);
                sc[nt][rr * 2]     = p0;
                sc[nt][rr * 2 + 1] = p1;
                rs += p0 + p1;
            }
            rs += __shfl_xor_sync(0xffffffffu, rs, 1);
            rs += __shfl_xor_sync(0xffffffffu, rs, 2);
            l_i[rr] = l_i[rr] * corr + rs;
            m_i[rr] = mn;
#pragma unroll
            for (int nt = 0; nt < 8; nt++) {
                o[nt][rr * 2]     *= corr;
                o[nt][rr * 2 + 1] *= corr;
            }
        }

        __syncthreads();   // everyone done reading KP as K
        // Write P into KP (rows are warp-private)
#pragma unroll
        for (int nt = 0; nt < 8; nt++)
#pragma unroll
            for (int rr = 0; rr < 2; rr++) {
                int row = m0 + g + rr * 8;
                int col = nt * 8 + 2 * t;
                uint2 u = make_uint2(f2tf(sc[nt][rr * 2]), f2tf(sc[nt][rr * 2 + 1]));
                *(uint2*)&KP[row * 68 + col] = u;
            }
        __syncwarp();

        // O += P @ V
#pragma unroll
        for (int kk = 0; kk < 8; kk++) {
            const int kb = kk * 8;
            uint32_t a0 = KP[(m0 + g)     * 68 + kb + t];
            uint32_t a1 = KP[(m0 + g + 8) * 68 + kb + t];
            uint32_t a2 = KP[(m0 + g)     * 68 + kb + t + 4];
            uint32_t a3 = KP[(m0 + g + 8) * 68 + kb + t + 4];
#pragma unroll
            for (int nt = 0; nt < 8; nt++) {
                uint32_t b0 = Vs[(kb + t)     * 68 + nt * 8 + g];
                uint32_t b1 = Vs[(kb + t + 4) * 68 + nt * 8 + g];
                mma_tf32(o[nt], a0, a1, a2, a3, b0, b1);
            }
        }
    }

    // Epilogue
    const int b_ = bh >> 4;
    const int h  = bh & 15;
#pragma unroll
    for (int rr = 0; rr < 2; rr++) {
        int   q   = q0 + m0 + g + rr * 8;
        float inv = 1.f / l_i[rr];
#pragma unroll
        for (int nt = 0; nt < 8; nt++) {
            float2 rv = make_float2(o[nt][rr * 2] * inv, o[nt][rr * 2 + 1] * inv);
            *(float2*)&g_ctx[((size_t)(b_ * T_ + q)) * D_ + h * DK_ + nt * 8 + 2 * t] = rv;
        }
        if (t == 0) {
            g_m[(size_t)bh * T_ + q] = m_i[rr];
            g_l[(size_t)bh * T_ + q] = l_i[rr];
        }
    }
}

// ---------------------------------------------------------------------------
// Attn writeout: recompute S with mma, write exp(s-m)/l; zeros above diagonal.
// ---------------------------------------------------------------------------
__global__ __launch_bounds__(128) void attn_out_kernel(float* __restrict__ attn_base)
{
    __shared__ uint32_t Qs[64 * 68];
    __shared__ uint32_t Ks[64 * 68];

    const int tid  = threadIdx.x;
    const int wid  = tid >> 5;
    const int lane = tid & 31;
    const int g    = lane >> 2;
    const int t    = lane & 3;
    const int qt   = blockIdx.x;
    const int bh   = blockIdx.y;
    const int q0   = qt * 64;
    const int m0   = wid * 16;

    const float* Qg   = g_Q + (size_t)bh * T_ * DK_;
    const float* Kg   = g_K + (size_t)bh * T_ * DK_;
    float*       attn = attn_base + (size_t)bh * T_ * T_;

#pragma unroll
    for (int l = 0; l < 8; l++) {
        int idx = tid + l * 128;
        int r   = idx >> 4;
        int c4  = (idx & 15) * 4;
        float4 v = *(const float4*)&Qg[(size_t)(q0 + r) * DK_ + c4];
        *(uint4*)&Qs[r * 68 + c4] =
            make_uint4(f2tf(v.x * SCALE), f2tf(v.y * SCALE),
                       f2tf(v.z * SCALE), f2tf(v.w * SCALE));
    }

    float mrow[2], linv[2];
#pragma unroll
    for (int rr = 0; rr < 2; rr++) {
        int q = q0 + m0 + g + rr * 8;
        mrow[rr] = g_m[(size_t)bh * T_ + q];
        linv[rr] = 1.f / g_l[(size_t)bh * T_ + q];
    }
    __syncthreads();

    for (int kt = 0; kt < 32; kt++) {
        const int k0 = kt * 64;
        if (kt > qt) {
            float4 z = make_float4(0.f, 0.f, 0.f, 0.f);
#pragma unroll
            for (int l = 0; l < 8; l++) {
                int idx = tid + l * 128;
                int r   = idx >> 4;
                int c4  = (idx & 15) * 4;
                *(float4*)&attn[(size_t)(q0 + r) * T_ + k0 + c4] = z;
            }
            continue;
        }

        __syncthreads();
#pragma unroll
        for (int l = 0; l < 8; l++) {
            int idx = tid + l * 128;
            int r   = idx >> 4;
            int c4  = (idx & 15) * 4;
            float4 kv = *(const float4*)&Kg[(size_t)(k0 + r) * DK_ + c4];
            *(uint4*)&Ks[r * 68 + c4] =
                make_uint4(f2tf(kv.x), f2tf(kv.y), f2tf(kv.z), f2tf(kv.w));
        }
        __syncthreads();

        float sc[8][4];
#pragma unroll
        for (int nt = 0; nt < 8; nt++)
#pragma unroll
            for (int r = 0; r < 4; r++) sc[nt][r] = 0.f;
#pragma unroll
        for (int kk = 0; kk < 8; kk++) {
            const int kb = kk * 8;
            uint32_t a0 = Qs[(m0 + g)     * 68 + kb + t];
            uint32_t a1 = Qs[(m0 + g + 8) * 68 + kb + t];
            uint32_t a2 = Qs[(m0 + g)     * 68 + kb + t + 4];
            uint32_t a3 = Qs[(m0 + g + 8) * 68 + kb + t + 4];
#pragma unroll
            for (int nt = 0; nt < 8; nt++) {
                uint32_t b0 = Ks[(nt * 8 + g) * 68 + kb + t];
                uint32_t b1 = Ks[(nt * 8 + g) * 68 + kb + t + 4];
                mma_tf32(sc[nt], a0, a1, a2, a3, b0, b1);
            }
        }

#pragma unroll
        for (int rr = 0; rr < 2; rr++) {
            int q = q0 + m0 + g + rr * 8;
#pragma unroll
            for (int nt = 0; nt < 8; nt++) {
                int col = k0 + nt * 8 + 2 * t;
                float p0 = (col     <= q) ? __expf(sc[nt][rr * 2]     - mrow[rr]) * linv[rr] : 0.f;
                float p1 = (col + 1 <= q) ? __expf(sc[nt][rr * 2 + 1] - mrow[rr]) * linv[rr] : 0.f;
                *(float2*)&attn[(size_t)q * T_ + col] = make_float2(p0, p1);
            }
        }
    }
}

// ---------------------------------------------------------------------------
extern "C" void kernel_launch(void* const* d_in, const int* in_sizes, int n_in,
                              void* d_out, int out_size)
{
    (void)in_sizes; (void)n_in; (void)out_size;
    const float* q_inp = (const float*)d_in[0];
    const float* k_inp = (const float*)d_in[1];
    const float* v_inp = (const float*)d_in[2];
    const float* Wq = (const float*)d_in[4];
    const float* bq = (const float*)d_in[5];
    const float* Wk = (const float*)d_in[6];
    const float* bk = (const float*)d_in[7];
    const float* Wv = (const float*)d_in[8];
    const float* bv = (const float*)d_in[9];
    const float* Wo = (const float*)d_in[10];
    const float* bo = (const float*)d_in[11];
    float* out = (float*)d_out;

    const int FLASH_SMEM = 3 * 64 * 68 * 4;  // 52224 bytes
    cudaFuncSetAttribute(flash_kernel, cudaFuncAttributeMaxDynamicSharedMemorySize, FLASH_SMEM);

    qkv_kernel<<<dim3(8, 32, 3), 256>>>(q_inp, k_inp, v_inp, Wq, bq, Wk, bk, Wv, bv);
    flash_kernel<<<dim3(32, 32), 128, FLASH_SMEM>>>();
    attn_out_kernel<<<dim3(32, 32), 128>>>(out + OUT_ELEMS);
    outproj_kernel<<<dim3(8, 32), 256>>>(Wo, bo, out);
}

// round 4
// speedup vs baseline: 2.9862x; 1.0424x over previous
#include <cuda_runtime.h>
#include <math.h>
#include <stdint.h>

#define B_  2
#define T_  2048
#define D_  1024
#define H_  16
#define DK_ 64
constexpr long long OUT_ELEMS = (long long)B_ * T_ * D_;  // 4194304
constexpr float SCALE = 0.125f;

// Scratch (device globals)
__device__ float g_Q[B_*H_*T_*DK_];
__device__ float g_K[B_*H_*T_*DK_];
__device__ float g_V[B_*H_*T_*DK_];
__device__ float g_ctx[B_*T_*D_];
__device__ float g_m[B_*H_*T_];
__device__ float g_l[B_*H_*T_];

// ---------------------------------------------------------------------------
// Helpers
// ---------------------------------------------------------------------------
__device__ __forceinline__ uint32_t f2tf(float f) {
    uint32_t u;
    asm("cvt.rna.tf32.f32 %0, %1;" : "=r"(u) : "f"(f));
    return u;
}

__device__ __forceinline__ void mma_tf32(float c[4],
                                         uint32_t a0, uint32_t a1, uint32_t a2, uint32_t a3,
                                         uint32_t b0, uint32_t b1) {
    asm volatile(
        "mma.sync.aligned.m16n8k8.row.col.f32.tf32.tf32.f32 "
        "{%0,%1,%2,%3}, {%4,%5,%6,%7}, {%8,%9}, {%0,%1,%2,%3};"
        : "+f"(c[0]), "+f"(c[1]), "+f"(c[2]), "+f"(c[3])
        : "r"(a0), "r"(a1), "r"(a2), "r"(a3), "r"(b0), "r"(b1));
}

__device__ __forceinline__ void cp_async16(float* smem_dst, const float* gmem_src) {
    uint32_t s = (uint32_t)__cvta_generic_to_shared(smem_dst);
    asm volatile("cp.async.cg.shared.global [%0], [%1], 16;" :: "r"(s), "l"(gmem_src));
}
__device__ __forceinline__ void cp_commit() {
    asm volatile("cp.async.commit_group;");
}
template<int N>
__device__ __forceinline__ void cp_wait() {
    asm volatile("cp.async.wait_group %0;" :: "n"(N));
}

// ---------------------------------------------------------------------------
// Projection GEMM with cp.async 2-stage pipeline.
// BM=BN=128, BK=32, 256 threads = 8 warps (2x4), warp tile 64x32.
// Smem holds raw fp32; tf32 conversion at fragment load.
// ---------------------------------------------------------------------------
constexpr int AS_STRIDE = 36;    // 32 + 4 pad
constexpr int BS_STRIDE = 132;   // 128 + 4 pad
constexpr int AS_STAGE  = 128 * AS_STRIDE;
constexpr int BS_STAGE  = 32 * BS_STRIDE;
constexpr int GEMM_SMEM_BYTES = (2 * AS_STAGE + 2 * BS_STAGE) * 4;  // 70656

template<bool HEADSPLIT>
__device__ __forceinline__ void gemm_mma(const float* __restrict__ A,
                                         const float* __restrict__ W,
                                         const float* __restrict__ bias,
                                         float* __restrict__ out)
{
    extern __shared__ float gsm[];
    float* As = gsm;                  // [2][AS_STAGE]
    float* Bs = gsm + 2 * AS_STAGE;   // [2][BS_STAGE]

    const int tid  = threadIdx.x;
    const int wid  = tid >> 5;
    const int lane = tid & 31;
    const int g    = lane >> 2;
    const int t    = lane & 3;
    const int wm   = wid >> 2;
    const int wn   = wid & 3;
    const int rowBase = blockIdx.y * 128;
    const int colBase = blockIdx.x * 128;

    auto load_tiles = [&](int k0, int st) {
        float* Ad = As + st * AS_STAGE;
        float* Bd = Bs + st * BS_STAGE;
#pragma unroll
        for (int l = 0; l < 4; l++) {
            int idx = tid + l * 256;
            int r   = idx >> 3;
            int c4  = (idx & 7) * 4;
            cp_async16(&Ad[r * AS_STRIDE + c4],
                       &A[(size_t)(rowBase + r) * D_ + k0 + c4]);
        }
#pragma unroll
        for (int l = 0; l < 4; l++) {
            int idx = tid + l * 256;
            int r   = idx >> 5;
            int c4  = (idx & 31) * 4;
            cp_async16(&Bd[r * BS_STRIDE + c4],
                       &W[(size_t)(k0 + r) * D_ + colBase + c4]);
        }
    };

    float acc[4][4][4];
#pragma unroll
    for (int i = 0; i < 4; i++)
#pragma unroll
        for (int j = 0; j < 4; j++)
#pragma unroll
            for (int r = 0; r < 4; r++) acc[i][j][r] = 0.f;

    load_tiles(0, 0);
    cp_commit();

    int st = 0;
    for (int k0 = 0; k0 < D_; k0 += 32, st ^= 1) {
        if (k0 + 32 < D_) {
            load_tiles(k0 + 32, st ^ 1);
            cp_commit();
            cp_wait<1>();
        } else {
            cp_wait<0>();
        }
        __syncthreads();

        const float* Ac = As + st * AS_STAGE;
        const float* Bc = Bs + st * BS_STAGE;

#pragma unroll
        for (int kk = 0; kk < 4; kk++) {
            const int kb = kk * 8;
            uint32_t a[4][4];
#pragma unroll
            for (int mt = 0; mt < 4; mt++) {
                int m = wm * 64 + mt * 16;
                a[mt][0] = f2tf(Ac[(m + g)     * AS_STRIDE + kb + t]);
                a[mt][1] = f2tf(Ac[(m + g + 8) * AS_STRIDE + kb + t]);
                a[mt][2] = f2tf(Ac[(m + g)     * AS_STRIDE + kb + t + 4]);
                a[mt][3] = f2tf(Ac[(m + g + 8) * AS_STRIDE + kb + t + 4]);
            }
#pragma unroll
            for (int nt = 0; nt < 4; nt++) {
                int n = wn * 32 + nt * 8;
                uint32_t b0 = f2tf(Bc[(kb + t)     * BS_STRIDE + n + g]);
                uint32_t b1 = f2tf(Bc[(kb + t + 4) * BS_STRIDE + n + g]);
#pragma unroll
                for (int mt = 0; mt < 4; mt++)
                    mma_tf32(acc[mt][nt], a[mt][0], a[mt][1], a[mt][2], a[mt][3], b0, b1);
            }
        }
        __syncthreads();   // all reads of stage st done before it is refilled
    }

    // Epilogue
#pragma unroll
    for (int mt = 0; mt < 4; mt++) {
#pragma unroll
        for (int nt = 0; nt < 4; nt++) {
            int n = colBase + wn * 32 + nt * 8 + 2 * t;
            float2 bv = *(const float2*)&bias[n];
#pragma unroll
            for (int rr = 0; rr < 2; rr++) {
                int m = rowBase + wm * 64 + mt * 16 + g + rr * 8;
                float2 rv;
                rv.x = acc[mt][nt][rr * 2 + 0] + bv.x;
                rv.y = acc[mt][nt][rr * 2 + 1] + bv.y;
                if (HEADSPLIT) {
                    int b  = m >> 11;
                    int tt = m & (T_ - 1);
                    int h  = n >> 6;
                    int dk = n & 63;
                    *(float2*)&out[(((size_t)(b * H_ + h) * T_) + tt) * DK_ + dk] = rv;
                } else {
                    *(float2*)&out[(size_t)m * D_ + n] = rv;
                }
            }
        }
    }
}

__global__ __launch_bounds__(256) void qkv_kernel(
    const float* __restrict__ q_inp, const float* __restrict__ k_inp,
    const float* __restrict__ v_inp,
    const float* __restrict__ Wq, const float* __restrict__ bq,
    const float* __restrict__ Wk, const float* __restrict__ bk,
    const float* __restrict__ Wv, const float* __restrict__ bv)
{
    if (blockIdx.z == 0)      gemm_mma<true>(q_inp, Wq, bq, g_Q);
    else if (blockIdx.z == 1) gemm_mma<true>(k_inp, Wk, bk, g_K);
    else                      gemm_mma<true>(v_inp, Wv, bv, g_V);
}

__global__ __launch_bounds__(256) void outproj_kernel(
    const float* __restrict__ Wo, const float* __restrict__ bo,
    float* __restrict__ out)
{
    gemm_mma<false>(g_ctx, Wo, bo, out);
}

// ---------------------------------------------------------------------------
// Flash attention, tf32 mma, cp.async 2-stage K/V pipeline.
// 128 threads = 4 warps; q-tile 64, warp owns 16 q rows.
// Dyn smem: Qs(tf32) | Ks[2](f32) | Vs[2](f32) | Ps(tf32), stride 68.
// ---------------------------------------------------------------------------
constexpr int FT = 64 * 68;                       // one tile
constexpr int FLASH_SMEM_BYTES = 6 * FT * 4;      // 104448

__global__ __launch_bounds__(128) void flash_kernel()
{
    extern __shared__ float fsm[];
    uint32_t* Qs = (uint32_t*)fsm;          // [64][68] tf32, pre-scaled
    float*    Ks = fsm + FT;                // [2][64][68] raw f32
    float*    Vs = fsm + 3 * FT;            // [2][64][68] raw f32
    uint32_t* Ps = (uint32_t*)(fsm + 5 * FT);  // [64][68] tf32

    const int tid  = threadIdx.x;
    const int wid  = tid >> 5;
    const int lane = tid & 31;
    const int g    = lane >> 2;
    const int t    = lane & 3;
    const int qt   = blockIdx.x;
    const int bh   = blockIdx.y;
    const int q0   = qt * 64;
    const int m0   = wid * 16;

    const float* Qg = g_Q + (size_t)bh * T_ * DK_;
    const float* Kg = g_K + (size_t)bh * T_ * DK_;
    const float* Vg = g_V + (size_t)bh * T_ * DK_;

    auto load_kv = [&](int kt_, int st) {
        const float* Kp = Kg + (size_t)kt_ * 64 * DK_;
        const float* Vp = Vg + (size_t)kt_ * 64 * DK_;
        float* Kd = Ks + st * FT;
        float* Vd = Vs + st * FT;
#pragma unroll
        for (int l = 0; l < 8; l++) {
            int idx = tid + l * 128;
            int r   = idx >> 4;
            int c4  = (idx & 15) * 4;
            cp_async16(&Kd[r * 68 + c4], &Kp[(size_t)r * DK_ + c4]);
            cp_async16(&Vd[r * 68 + c4], &Vp[(size_t)r * DK_ + c4]);
        }
    };

    // Load Q tile (scaled, tf32)
#pragma unroll
    for (int l = 0; l < 8; l++) {
        int idx = tid + l * 128;
        int r   = idx >> 4;
        int c4  = (idx & 15) * 4;
        float4 v = *(const float4*)&Qg[(size_t)(q0 + r) * DK_ + c4];
        *(uint4*)&Qs[r * 68 + c4] =
            make_uint4(f2tf(v.x * SCALE), f2tf(v.y * SCALE),
                       f2tf(v.z * SCALE), f2tf(v.w * SCALE));
    }

    float m_i[2] = {-INFINITY, -INFINITY};
    float l_i[2] = {0.f, 0.f};
    float o[8][4];
#pragma unroll
    for (int nt = 0; nt < 8; nt++)
#pragma unroll
        for (int r = 0; r < 4; r++) o[nt][r] = 0.f;

    load_kv(0, 0);
    cp_commit();

    for (int kt = 0; kt <= qt; kt++) {
        const int st = kt & 1;
        const int k0 = kt * 64;

        __syncthreads();   // all warps done reading stage st^1 (and Qs stored, iter 0)
        if (kt < qt) {
            load_kv(kt + 1, st ^ 1);
            cp_commit();
            cp_wait<1>();
        } else {
            cp_wait<0>();
        }
        __syncthreads();   // K/V stage st visible

        const float* Kc = Ks + st * FT;
        const float* Vc = Vs + st * FT;

        // S = Q K^T
        float sc[8][4];
#pragma unroll
        for (int nt = 0; nt < 8; nt++)
#pragma unroll
            for (int r = 0; r < 4; r++) sc[nt][r] = 0.f;
#pragma unroll
        for (int kk = 0; kk < 8; kk++) {
            const int kb = kk * 8;
            uint32_t a0 = Qs[(m0 + g)     * 68 + kb + t];
            uint32_t a1 = Qs[(m0 + g + 8) * 68 + kb + t];
            uint32_t a2 = Qs[(m0 + g)     * 68 + kb + t + 4];
            uint32_t a3 = Qs[(m0 + g + 8) * 68 + kb + t + 4];
#pragma unroll
            for (int nt = 0; nt < 8; nt++) {
                uint32_t b0 = f2tf(Kc[(nt * 8 + g) * 68 + kb + t]);
                uint32_t b1 = f2tf(Kc[(nt * 8 + g) * 68 + kb + t + 4]);
                mma_tf32(sc[nt], a0, a1, a2, a3, b0, b1);
            }
        }

        // Causal mask on diagonal tile
        if (kt == qt) {
#pragma unroll
            for (int nt = 0; nt < 8; nt++)
#pragma unroll
                for (int r = 0; r < 4; r++) {
                    int row = q0 + m0 + g + (r >> 1) * 8;
                    int col = k0 + nt * 8 + 2 * t + (r & 1);
                    if (col > row) sc[nt][r] = -1e30f;
                }
        }

        // Online softmax
#pragma unroll
        for (int rr = 0; rr < 2; rr++) {
            float tm = -INFINITY;
#pragma unroll
            for (int nt = 0; nt < 8; nt++)
                tm = fmaxf(tm, fmaxf(sc[nt][rr * 2], sc[nt][rr * 2 + 1]));
            tm = fmaxf(tm, __shfl_xor_sync(0xffffffffu, tm, 1));
            tm = fmaxf(tm, __shfl_xor_sync(0xffffffffu, tm, 2));
            float mn   = fmaxf(m_i[rr], tm);
            float corr = __expf(m_i[rr] - mn);
            float rs = 0.f;
#pragma unroll
            for (int nt = 0; nt < 8; nt++) {
                float p0 = __expf(sc[nt][rr * 2]     - mn);
                float p1 = __expf(sc[nt][rr * 2 + 1] - mn);
                sc[nt][rr * 2]     = p0;
                sc[nt][rr * 2 + 1] = p1;
                rs += p0 + p1;
            }
            rs += __shfl_xor_sync(0xffffffffu, rs, 1);
            rs += __shfl_xor_sync(0xffffffffu, rs, 2);
            l_i[rr] = l_i[rr] * corr + rs;
            m_i[rr] = mn;
#pragma unroll
            for (int nt = 0; nt < 8; nt++) {
                o[nt][rr * 2]     *= corr;
                o[nt][rr * 2 + 1] *= corr;
            }
        }

        // Write P (tf32) to warp-private rows of Ps
#pragma unroll
        for (int nt = 0; nt < 8; nt++)
#pragma unroll
            for (int rr = 0; rr < 2; rr++) {
                int row = m0 + g + rr * 8;
                int col = nt * 8 + 2 * t;
                *(uint2*)&Ps[row * 68 + col] =
                    make_uint2(f2tf(sc[nt][rr * 2]), f2tf(sc[nt][rr * 2 + 1]));
            }
        __syncwarp();

        // O += P @ V
#pragma unroll
        for (int kk = 0; kk < 8; kk++) {
            const int kb = kk * 8;
            uint32_t a0 = Ps[(m0 + g)     * 68 + kb + t];
            uint32_t a1 = Ps[(m0 + g + 8) * 68 + kb + t];
            uint32_t a2 = Ps[(m0 + g)     * 68 + kb + t + 4];
            uint32_t a3 = Ps[(m0 + g + 8) * 68 + kb + t + 4];
#pragma unroll
            for (int nt = 0; nt < 8; nt++) {
                uint32_t b0 = f2tf(Vc[(kb + t)     * 68 + nt * 8 + g]);
                uint32_t b1 = f2tf(Vc[(kb + t + 4) * 68 + nt * 8 + g]);
                mma_tf32(o[nt], a0, a1, a2, a3, b0, b1);
            }
        }
    }

    // Epilogue
    const int b_ = bh >> 4;
    const int h  = bh & 15;
#pragma unroll
    for (int rr = 0; rr < 2; rr++) {
        int   q   = q0 + m0 + g + rr * 8;
        float inv = 1.f / l_i[rr];
#pragma unroll
        for (int nt = 0; nt < 8; nt++) {
            float2 rv = make_float2(o[nt][rr * 2] * inv, o[nt][rr * 2 + 1] * inv);
            *(float2*)&g_ctx[((size_t)(b_ * T_ + q)) * D_ + h * DK_ + nt * 8 + 2 * t] = rv;
        }
        if (t == 0) {
            g_m[(size_t)bh * T_ + q] = m_i[rr];
            g_l[(size_t)bh * T_ + q] = l_i[rr];
        }
    }
}

// ---------------------------------------------------------------------------
// Attn writeout: recompute S with mma, write exp(s-m)/l; zeros above diagonal.
// ---------------------------------------------------------------------------
__global__ __launch_bounds__(128) void attn_out_kernel(float* __restrict__ attn_base)
{
    __shared__ uint32_t Qs[64 * 68];
    __shared__ uint32_t Ks[64 * 68];

    const int tid  = threadIdx.x;
    const int wid  = tid >> 5;
    const int lane = tid & 31;
    const int g    = lane >> 2;
    const int t    = lane & 3;
    const int qt   = blockIdx.x;
    const int bh   = blockIdx.y;
    const int q0   = qt * 64;
    const int m0   = wid * 16;

    const float* Qg   = g_Q + (size_t)bh * T_ * DK_;
    const float* Kg   = g_K + (size_t)bh * T_ * DK_;
    float*       attn = attn_base + (size_t)bh * T_ * T_;

#pragma unroll
    for (int l = 0; l < 8; l++) {
        int idx = tid + l * 128;
        int r   = idx >> 4;
        int c4  = (idx & 15) * 4;
        float4 v = *(const float4*)&Qg[(size_t)(q0 + r) * DK_ + c4];
        *(uint4*)&Qs[r * 68 + c4] =
            make_uint4(f2tf(v.x * SCALE), f2tf(v.y * SCALE),
                       f2tf(v.z * SCALE), f2tf(v.w * SCALE));
    }

    float mrow[2], linv[2];
#pragma unroll
    for (int rr = 0; rr < 2; rr++) {
        int q = q0 + m0 + g + rr * 8;
        mrow[rr] = g_m[(size_t)bh * T_ + q];
        linv[rr] = 1.f / g_l[(size_t)bh * T_ + q];
    }
    __syncthreads();

    for (int kt = 0; kt < 32; kt++) {
        const int k0 = kt * 64;
        if (kt > qt) {
            float4 z = make_float4(0.f, 0.f, 0.f, 0.f);
#pragma unroll
            for (int l = 0; l < 8; l++) {
                int idx = tid + l * 128;
                int r   = idx >> 4;
                int c4  = (idx & 15) * 4;
                *(float4*)&attn[(size_t)(q0 + r) * T_ + k0 + c4] = z;
            }
            continue;
        }

        __syncthreads();
#pragma unroll
        for (int l = 0; l < 8; l++) {
            int idx = tid + l * 128;
            int r   = idx >> 4;
            int c4  = (idx & 15) * 4;
            float4 kv = *(const float4*)&Kg[(size_t)(k0 + r) * DK_ + c4];
            *(uint4*)&Ks[r * 68 + c4] =
                make_uint4(f2tf(kv.x), f2tf(kv.y), f2tf(kv.z), f2tf(kv.w));
        }
        __syncthreads();

        float sc[8][4];
#pragma unroll
        for (int nt = 0; nt < 8; nt++)
#pragma unroll
            for (int r = 0; r < 4; r++) sc[nt][r] = 0.f;
#pragma unroll
        for (int kk = 0; kk < 8; kk++) {
            const int kb = kk * 8;
            uint32_t a0 = Qs[(m0 + g)     * 68 + kb + t];
            uint32_t a1 = Qs[(m0 + g + 8) * 68 + kb + t];
            uint32_t a2 = Qs[(m0 + g)     * 68 + kb + t + 4];
            uint32_t a3 = Qs[(m0 + g + 8) * 68 + kb + t + 4];
#pragma unroll
            for (int nt = 0; nt < 8; nt++) {
                uint32_t b0 = Ks[(nt * 8 + g) * 68 + kb + t];
                uint32_t b1 = Ks[(nt * 8 + g) * 68 + kb + t + 4];
                mma_tf32(sc[nt], a0, a1, a2, a3, b0, b1);
            }
        }

#pragma unroll
        for (int rr = 0; rr < 2; rr++) {
            int q = q0 + m0 + g + rr * 8;
#pragma unroll
            for (int nt = 0; nt < 8; nt++) {
                int col = k0 + nt * 8 + 2 * t;
                float p0 = (col     <= q) ? __expf(sc[nt][rr * 2]     - mrow[rr]) * linv[rr] : 0.f;
                float p1 = (col + 1 <= q) ? __expf(sc[nt][rr * 2 + 1] - mrow[rr]) * linv[rr] : 0.f;
                *(float2*)&attn[(size_t)q * T_ + col] = make_float2(p0, p1);
            }
        }
    }
}

// ---------------------------------------------------------------------------
extern "C" void kernel_launch(void* const* d_in, const int* in_sizes, int n_in,
                              void* d_out, int out_size)
{
    (void)in_sizes; (void)n_in; (void)out_size;
    const float* q_inp = (const float*)d_in[0];
    const float* k_inp = (const float*)d_in[1];
    const float* v_inp = (const float*)d_in[2];
    const float* Wq = (const float*)d_in[4];
    const float* bq = (const float*)d_in[5];
    const float* Wk = (const float*)d_in[6];
    const float* bk = (const float*)d_in[7];
    const float* Wv = (const float*)d_in[8];
    const float* bv = (const float*)d_in[9];
    const float* Wo = (const float*)d_in[10];
    const float* bo = (const float*)d_in[11];
    float* out = (float*)d_out;

    cudaFuncSetAttribute(qkv_kernel,     cudaFuncAttributeMaxDynamicSharedMemorySize, GEMM_SMEM_BYTES);
    cudaFuncSetAttribute(outproj_kernel, cudaFuncAttributeMaxDynamicSharedMemorySize, GEMM_SMEM_BYTES);
    cudaFuncSetAttribute(flash_kernel,   cudaFuncAttributeMaxDynamicSharedMemorySize, FLASH_SMEM_BYTES);

    qkv_kernel<<<dim3(8, 32, 3), 256, GEMM_SMEM_BYTES>>>(q_inp, k_inp, v_inp,
                                                         Wq, bq, Wk, bk, Wv, bv);
    flash_kernel<<<dim3(32, 32), 128, FLASH_SMEM_BYTES>>>();
    attn_out_kernel<<<dim3(32, 32), 128>>>(out + OUT_ELEMS);
    outproj_kernel<<<dim3(8, 32), 256, GEMM_SMEM_BYTES>>>(Wo, bo, out);
}